// round 15
// baseline (speedup 1.0000x reference)
#include <cuda_runtime.h>
#include <cstdint>

// Problem constants
#define BB 2048
#define TT 2
#define NTOK 64
#define CDIM 256
#define NH 8

// Scratch (device globals; allocation APIs are forbidden)
__device__ float g_q[(size_t)BB * NTOK * CDIM];
__device__ float g_bias[NH * NTOK * NTOK];      // [h][n][m] precomputed rpb
__device__ float g_wq[CDIM * CDIM];             // tf32-pre-converted weights
__device__ float g_wkv[2 * CDIM * CDIM];
__device__ float g_wp[CDIM * CDIM];

// ---- tf32 helpers -----------------------------------------------------------
__device__ __forceinline__ uint32_t f2tf32(float f) {
    uint32_t r;
    asm("cvt.rna.tf32.f32 %0, %1;" : "=r"(r) : "f"(f));
    return r;
}
__device__ __forceinline__ void mma_tf32(float c[4], const uint32_t a[4],
                                         const uint32_t b[2]) {
    asm("mma.sync.aligned.m16n8k8.row.col.f32.tf32.tf32.f32 "
        "{%0,%1,%2,%3}, {%4,%5,%6,%7}, {%8,%9}, {%0,%1,%2,%3};"
        : "+f"(c[0]), "+f"(c[1]), "+f"(c[2]), "+f"(c[3])
        : "r"(a[0]), "r"(a[1]), "r"(a[2]), "r"(a[3]), "r"(b[0]), "r"(b[1]));
}

// ---- cp.async helpers -------------------------------------------------------
__device__ __forceinline__ void cp16(float* smem_dst, const float* gsrc) {
    uint32_t s = (uint32_t)__cvta_generic_to_shared(smem_dst);
    asm volatile("cp.async.cg.shared.global [%0], [%1], 16;" :: "r"(s), "l"(gsrc));
}
__device__ __forceinline__ void cp_commit() {
    asm volatile("cp.async.commit_group;");
}
__device__ __forceinline__ void cp_wait1() {
    asm volatile("cp.async.wait_group 1;");
}
__device__ __forceinline__ void cp_wait0() {
    asm volatile("cp.async.wait_group 0;");
}

// ---------------------------------------------------------------------------
// Fused prologue: bias table + 3 weight tf32 conversions. 1152 blocks x 256.
// ---------------------------------------------------------------------------
__global__ __launch_bounds__(256) void prolog(
    const float* __restrict__ rpb, const float* __restrict__ qw,
    const float* __restrict__ kvw, const float* __restrict__ pw)
{
    int i = blockIdx.x * 256 + threadIdx.x;
    if (i < 32768) {
        int h = i >> 12, n = (i >> 6) & 63, m = i & 63;
        int idx = ((n >> 3) - (m >> 3) + 7) * 15 + ((n & 7) - (m & 7) + 7);
        g_bias[i] = rpb[idx * 8 + h];
    } else if (i < 98304) {
        int j = i - 32768;
        g_wq[j] = __uint_as_float(f2tf32(qw[j]));
    } else if (i < 229376) {
        int j = i - 98304;
        g_wkv[j] = __uint_as_float(f2tf32(kvw[j]));
    } else {
        int j = i - 229376;
        g_wp[j] = __uint_as_float(f2tf32(pw[j]));
    }
}

// ---------------------------------------------------------------------------
// TF32 GEMM (round-13 proven): C[M,N] = A[M,K] @ W[N,K]^T + bias[N].
// Used only for the q projection now.
// ---------------------------------------------------------------------------
#define A_TW (256 * 36)
#define W_TW (128 * 36)
#define GEMM_SMEM_BYTES (2 * (A_TW + W_TW) * 4)

__global__ __launch_bounds__(256, 1) void gemm_tf32(
    const float* __restrict__ A, const float* __restrict__ Wt,
    const float* __restrict__ bias, float* __restrict__ C,
    int M, int N, int K)
{
    extern __shared__ float gsm[];
    float* Asm = gsm;
    float* Wsm = gsm + 2 * A_TW;

    const int tid  = threadIdx.x;
    const int wid  = tid >> 5;
    const int lane = tid & 31;
    const int g    = lane >> 2;
    const int tig  = lane & 3;
    const int bm = blockIdx.y * 256;
    const int bn = blockIdx.x * 128;
    const int warp_m = (wid >> 1) * 64;
    const int warp_n = (wid & 1) * 64;

    const int srow = tid >> 3;
    const int sc4  = (tid & 7) * 4;
    const float* Abase = A + (size_t)(bm + srow) * K + sc4;
    const float* Wbase = Wt + (size_t)(bn + srow) * K + sc4;

    float acc[4][8][4];
#pragma unroll
    for (int i = 0; i < 4; i++)
#pragma unroll
        for (int j = 0; j < 8; j++)
#pragma unroll
            for (int r = 0; r < 4; r++) acc[i][j][r] = 0.0f;

    const int nk = K >> 5;
    {
#pragma unroll
        for (int c = 0; c < 8; c++)
            cp16(Asm + (srow + 32 * c) * 36 + sc4, Abase + (size_t)(32 * c) * K);
#pragma unroll
        for (int c = 0; c < 4; c++)
            cp16(Wsm + (srow + 32 * c) * 36 + sc4, Wbase + (size_t)(32 * c) * K);
        cp_commit();
    }

    for (int kt = 0; kt < nk; kt++) {
        const int cur = kt & 1;
        if (kt + 1 < nk) {
            float* Ad = Asm + (1 - cur) * A_TW;
            float* Wd = Wsm + (1 - cur) * W_TW;
            const float* Ag = Abase + (kt + 1) * 32;
            const float* Wg = Wbase + (kt + 1) * 32;
#pragma unroll
            for (int c = 0; c < 8; c++)
                cp16(Ad + (srow + 32 * c) * 36 + sc4, Ag + (size_t)(32 * c) * K);
#pragma unroll
            for (int c = 0; c < 4; c++)
                cp16(Wd + (srow + 32 * c) * 36 + sc4, Wg + (size_t)(32 * c) * K);
            cp_commit();
            cp_wait1();
        } else {
            cp_wait0();
        }
        __syncthreads();

        const float* Ab = Asm + cur * A_TW;
        const float* Wb = Wsm + cur * W_TW;
#pragma unroll
        for (int kk = 0; kk < 4; kk++) {
            const int kb = kk * 8;
            uint32_t af[4][4], bf[8][2];
#pragma unroll
            for (int i = 0; i < 4; i++) {
                int row = warp_m + i * 16;
                af[i][0] = f2tf32(Ab[(row + g) * 36 + kb + tig]);
                af[i][1] = f2tf32(Ab[(row + 8 + g) * 36 + kb + tig]);
                af[i][2] = f2tf32(Ab[(row + g) * 36 + kb + tig + 4]);
                af[i][3] = f2tf32(Ab[(row + 8 + g) * 36 + kb + tig + 4]);
            }
#pragma unroll
            for (int j = 0; j < 8; j++) {
                int col = warp_n + j * 8 + g;
                bf[j][0] = __float_as_uint(Wb[col * 36 + kb + tig]);
                bf[j][1] = __float_as_uint(Wb[col * 36 + kb + tig + 4]);
            }
#pragma unroll
            for (int i = 0; i < 4; i++)
#pragma unroll
                for (int j = 0; j < 8; j++)
                    mma_tf32(acc[i][j], af[i], bf[j]);
        }
        __syncthreads();
    }

#pragma unroll
    for (int j = 0; j < 8; j++) {
        int col = bn + warp_n + j * 8 + tig * 2;
        float b0 = bias[col], b1 = bias[col + 1];
#pragma unroll
        for (int i = 0; i < 4; i++) {
            int row = bm + warp_m + i * 16 + g;
            float2 v0 = make_float2(acc[i][j][0] + b0, acc[i][j][1] + b1);
            float2 v1 = make_float2(acc[i][j][2] + b0, acc[i][j][3] + b1);
            *reinterpret_cast<float2*>(C + (size_t)row * N + col) = v0;
            *reinterpret_cast<float2*>(C + (size_t)(row + 8) * N + col) = v1;
        }
    }
}

// ---------------------------------------------------------------------------
// MEGA kernel: block = (b, t), 256 threads = 8 warps.
// Phase 1: KV = memory[bt] @ kv_w^T + kv_b  -> K,V in smem (tf32 bits)
// Phase 2: per head: QK^T (+bias), softmax, PV -> O in smem (fp32)
// Phase 3: out = O @ proj_w^T + proj_b -> gmem
// Smem (floats): KS[64x260]@0, VS[64x264]@16640, QH[64x36]@33536 (sums at +34),
// SS[64x68]@35840, OO[64x258]@40192. Phase-1 staging A1@33536/W1@36096
// overlays QH/SS/OO; phase-3 W staging overlays KS. Total 226,816 B.
// ---------------------------------------------------------------------------
#define KS_OFF 0
#define VS_OFF 16640
#define QH_OFF 33536
#define SS_OFF 35840
#define OO_OFF 40192
#define A1_OFF 33536
#define W1_OFF 36096
#define WP_OFF 0
#define MEGA_SMEM_BYTES (56704 * 4)

__global__ __launch_bounds__(256, 1) void mega(
    const float* __restrict__ memory, const float* __restrict__ kv_b,
    const float* __restrict__ proj_b, float* __restrict__ out)
{
    extern __shared__ float S[];
    const int tid  = threadIdx.x;
    const int wid  = tid >> 5;
    const int lane = tid & 31;
    const int g    = lane >> 2;
    const int tig  = lane & 3;
    const int bt   = blockIdx.x;
    const int b    = bt >> 1;

    // ================= Phase 1: KV projection (64 x 512, K=256) =============
    {
        const int warp_n = wid * 64;
        const int srow = tid >> 2;        // 0..63
        const int sc4  = (tid & 3) * 4;
        const int wrow = tid >> 2;        // base row for W staging
        const float* Abase = memory + (size_t)(bt * 64 + srow) * 256 + sc4;

        float acc[4][8][4];
#pragma unroll
        for (int i = 0; i < 4; i++)
#pragma unroll
            for (int j = 0; j < 8; j++)
#pragma unroll
                for (int r = 0; r < 4; r++) acc[i][j][r] = 0.0f;

        // prologue: stage kt=0
        cp16(S + A1_OFF + srow * 20 + sc4, Abase);
#pragma unroll
        for (int c = 0; c < 8; c++) {
            int row = wrow + 64 * c;
            cp16(S + W1_OFF + row * 20 + sc4, g_wkv + (size_t)row * 256 + sc4);
        }
        cp_commit();

        for (int kt = 0; kt < 16; kt++) {
            const int cur = kt & 1;
            if (kt + 1 < 16) {
                const int k0 = (kt + 1) * 16;
                cp16(S + A1_OFF + (1 - cur) * 1280 + srow * 20 + sc4, Abase + k0);
#pragma unroll
                for (int c = 0; c < 8; c++) {
                    int row = wrow + 64 * c;
                    cp16(S + W1_OFF + (1 - cur) * 10240 + row * 20 + sc4,
                         g_wkv + (size_t)row * 256 + k0 + sc4);
                }
                cp_commit();
                cp_wait1();
            } else {
                cp_wait0();
            }
            __syncthreads();

            const float* Ab = S + A1_OFF + cur * 1280;
            const float* Wb = S + W1_OFF + cur * 10240;
#pragma unroll
            for (int kk = 0; kk < 2; kk++) {
                const int kb = kk * 8;
                uint32_t af[4][4], bf[8][2];
#pragma unroll
                for (int i = 0; i < 4; i++) {
                    int row = i * 16;
                    af[i][0] = f2tf32(Ab[(row + g) * 20 + kb + tig]);
                    af[i][1] = f2tf32(Ab[(row + 8 + g) * 20 + kb + tig]);
                    af[i][2] = f2tf32(Ab[(row + g) * 20 + kb + tig + 4]);
                    af[i][3] = f2tf32(Ab[(row + 8 + g) * 20 + kb + tig + 4]);
                }
#pragma unroll
                for (int j = 0; j < 8; j++) {
                    int col = warp_n + j * 8 + g;
                    bf[j][0] = __float_as_uint(Wb[col * 20 + kb + tig]);
                    bf[j][1] = __float_as_uint(Wb[col * 20 + kb + tig + 4]);
                }
#pragma unroll
                for (int i = 0; i < 4; i++)
#pragma unroll
                    for (int j = 0; j < 8; j++)
                        mma_tf32(acc[i][j], af[i], bf[j]);
            }
            __syncthreads();
        }

        // epilogue: + kv_b, cvt tf32, store K (ch<256) / V (ch>=256)
#pragma unroll
        for (int j = 0; j < 8; j++) {
            int ch = warp_n + j * 8 + 2 * tig;
            float b0 = kv_b[ch], b1 = kv_b[ch + 1];
            int base, stride, cc;
            if (ch < 256) { base = KS_OFF; stride = 260; cc = ch; }
            else          { base = VS_OFF; stride = 264; cc = ch - 256; }
#pragma unroll
            for (int i = 0; i < 4; i++) {
                int r0 = i * 16 + g, r1 = r0 + 8;
                float2 v0 = make_float2(
                    __uint_as_float(f2tf32(acc[i][j][0] + b0)),
                    __uint_as_float(f2tf32(acc[i][j][1] + b1)));
                float2 v1 = make_float2(
                    __uint_as_float(f2tf32(acc[i][j][2] + b0)),
                    __uint_as_float(f2tf32(acc[i][j][3] + b1)));
                *reinterpret_cast<float2*>(S + base + r0 * stride + cc) = v0;
                *reinterpret_cast<float2*>(S + base + r1 * stride + cc) = v1;
            }
        }
    }
    __syncthreads();

    // ================= Phase 2: attention per head ==========================
    const float scale = 0.17677669529663687f;  // 32^-0.5
    for (int h = 0; h < 8; h++) {
        // stage Q head (cvt + scale)
#pragma unroll
        for (int it = 0; it < 2; it++) {
            int id = tid + 256 * it;      // 0..511 float4s
            int r = id >> 3, c4 = id & 7;
            float4 qv = *reinterpret_cast<const float4*>(
                g_q + (size_t)(b * 64 + r) * 256 + h * 32 + c4 * 4);
            float4 qt;
            qt.x = __uint_as_float(f2tf32(qv.x * scale));
            qt.y = __uint_as_float(f2tf32(qv.y * scale));
            qt.z = __uint_as_float(f2tf32(qv.z * scale));
            qt.w = __uint_as_float(f2tf32(qv.w * scale));
            *reinterpret_cast<float4*>(S + QH_OFF + r * 36 + c4 * 4) = qt;
        }
        __syncthreads();

        // QK^T: warp (wm 0..3 rows, wn 0..1 cols)
        {
            const int wm = wid & 3, wn = wid >> 2;
            const int rb = 16 * wm, cb0 = 32 * wn;
            float acc[4][4];
#pragma unroll
            for (int j = 0; j < 4; j++)
#pragma unroll
                for (int r = 0; r < 4; r++) acc[j][r] = 0.0f;

#pragma unroll
            for (int k = 0; k < 4; k++) {
                uint32_t af[4];
                af[0] = __float_as_uint(S[QH_OFF + (rb + g) * 36 + 8 * k + tig]);
                af[1] = __float_as_uint(S[QH_OFF + (rb + 8 + g) * 36 + 8 * k + tig]);
                af[2] = __float_as_uint(S[QH_OFF + (rb + g) * 36 + 8 * k + tig + 4]);
                af[3] = __float_as_uint(S[QH_OFF + (rb + 8 + g) * 36 + 8 * k + tig + 4]);
#pragma unroll
                for (int jn = 0; jn < 4; jn++) {
                    int col = cb0 + 8 * jn + g;
                    uint32_t bf[2];
                    bf[0] = __float_as_uint(S[KS_OFF + col * 260 + h * 32 + 8 * k + tig]);
                    bf[1] = __float_as_uint(S[KS_OFF + col * 260 + h * 32 + 8 * k + tig + 4]);
                    mma_tf32(acc[jn], af, bf);
                }
            }
            const float* bh = g_bias + h * 4096;
#pragma unroll
            for (int jn = 0; jn < 4; jn++) {
                int cb = cb0 + 8 * jn + 2 * tig;
                float2 bv0 = __ldg(reinterpret_cast<const float2*>(bh + (rb + g) * 64 + cb));
                float2 bv1 = __ldg(reinterpret_cast<const float2*>(bh + (rb + 8 + g) * 64 + cb));
                *reinterpret_cast<float2*>(S + SS_OFF + (rb + g) * 68 + cb) =
                    make_float2(acc[jn][0] + bv0.x, acc[jn][1] + bv0.y);
                *reinterpret_cast<float2*>(S + SS_OFF + (rb + 8 + g) * 68 + cb) =
                    make_float2(acc[jn][2] + bv1.x, acc[jn][3] + bv1.y);
            }
        }
        __syncthreads();

        // softmax: 4 threads per row, 16 elems each
        {
            const int r = tid >> 2, qq = tid & 3;
            float* Sr = S + SS_OFF + r * 68 + qq * 16;
            float mx = -1e30f;
#pragma unroll
            for (int m = 0; m < 16; m++) mx = fmaxf(mx, Sr[m]);
            mx = fmaxf(mx, __shfl_xor_sync(0xFFFFFFFFu, mx, 1));
            mx = fmaxf(mx, __shfl_xor_sync(0xFFFFFFFFu, mx, 2));
            float sum = 0.0f;
#pragma unroll
            for (int m = 0; m < 16; m++) {
                float e = __expf(Sr[m] - mx);
                sum += e;
                Sr[m] = __uint_as_float(f2tf32(e));
            }
            sum += __shfl_xor_sync(0xFFFFFFFFu, sum, 1);
            sum += __shfl_xor_sync(0xFFFFFFFFu, sum, 2);
            if (qq == 0) S[QH_OFF + r * 36 + 34] = 1.0f / sum;
        }
        __syncthreads();

        // PV: warp (wm 0..3 rows, wd 0..1 dim-halves)
        {
            const int wm = wid & 3, wd = wid >> 2;
            const int rb = 16 * wm, db = 16 * wd;
            float acc[2][4];
#pragma unroll
            for (int j = 0; j < 2; j++)
#pragma unroll
                for (int r = 0; r < 4; r++) acc[j][r] = 0.0f;

#pragma unroll
            for (int k = 0; k < 8; k++) {
                uint32_t ah[4];
                ah[0] = __float_as_uint(S[SS_OFF + (rb + g) * 68 + 8 * k + tig]);
                ah[1] = __float_as_uint(S[SS_OFF + (rb + 8 + g) * 68 + 8 * k + tig]);
                ah[2] = __float_as_uint(S[SS_OFF + (rb + g) * 68 + 8 * k + tig + 4]);
                ah[3] = __float_as_uint(S[SS_OFF + (rb + 8 + g) * 68 + 8 * k + tig + 4]);
#pragma unroll
                for (int j = 0; j < 2; j++) {
                    uint32_t bf[2];
                    bf[0] = __float_as_uint(S[VS_OFF + (8 * k + tig) * 264 + h * 32 + db + 8 * j + g]);
                    bf[1] = __float_as_uint(S[VS_OFF + (8 * k + tig + 4) * 264 + h * 32 + db + 8 * j + g]);
                    mma_tf32(acc[j], ah, bf);
                }
            }
            float is0 = S[QH_OFF + (rb + g) * 36 + 34];
            float is1 = S[QH_OFF + (rb + 8 + g) * 36 + 34];
#pragma unroll
            for (int j = 0; j < 2; j++) {
                int d = h * 32 + db + 8 * j + 2 * tig;
                *reinterpret_cast<float2*>(S + OO_OFF + (rb + g) * 258 + d) =
                    make_float2(acc[j][0] * is0, acc[j][1] * is0);
                *reinterpret_cast<float2*>(S + OO_OFF + (rb + 8 + g) * 258 + d) =
                    make_float2(acc[j][2] * is1, acc[j][3] * is1);
            }
        }
    }

    // ================= Phase 3: out projection (64 x 256, K=256) ============
    {
        const int wm = wid & 1, wn = wid >> 1;
        const int wrow = tid >> 2;
        const int sc4  = (tid & 3) * 4;

        float acc[2][8][4];
#pragma unroll
        for (int i = 0; i < 2; i++)
#pragma unroll
            for (int j = 0; j < 8; j++)
#pragma unroll
                for (int r = 0; r < 4; r++) acc[i][j][r] = 0.0f;

        // stage kt=0 of proj_w (KS region is dead now)
#pragma unroll
        for (int c = 0; c < 4; c++) {
            int row = wrow + 64 * c;
            cp16(S + WP_OFF + row * 20 + sc4, g_wp + (size_t)row * 256 + sc4);
        }
        cp_commit();

        for (int kt = 0; kt < 16; kt++) {
            const int cur = kt & 1;
            if (kt + 1 < 16) {
                const int k0 = (kt + 1) * 16;
#pragma unroll
                for (int c = 0; c < 4; c++) {
                    int row = wrow + 64 * c;
                    cp16(S + WP_OFF + (1 - cur) * 5120 + row * 20 + sc4,
                         g_wp + (size_t)row * 256 + k0 + sc4);
                }
                cp_commit();
                cp_wait1();
            } else {
                cp_wait0();
            }
            __syncthreads();

            const float* Wb = S + WP_OFF + cur * 5120;
#pragma unroll
            for (int kk = 0; kk < 2; kk++) {
                const int kb = kk * 8;
                const int kg = kt * 16 + kb;
                uint32_t af[2][4], bf[8][2];
#pragma unroll
                for (int i = 0; i < 2; i++) {
                    int row = 32 * wm + i * 16;
                    af[i][0] = f2tf32(S[OO_OFF + (row + g) * 258 + kg + tig]);
                    af[i][1] = f2tf32(S[OO_OFF + (row + 8 + g) * 258 + kg + tig]);
                    af[i][2] = f2tf32(S[OO_OFF + (row + g) * 258 + kg + tig + 4]);
                    af[i][3] = f2tf32(S[OO_OFF + (row + 8 + g) * 258 + kg + tig + 4]);
                }
#pragma unroll
                for (int j = 0; j < 8; j++) {
                    int col = 64 * wn + 8 * j + g;
                    bf[j][0] = __float_as_uint(Wb[col * 20 + kb + tig]);
                    bf[j][1] = __float_as_uint(Wb[col * 20 + kb + tig + 4]);
                }
#pragma unroll
                for (int i = 0; i < 2; i++)
#pragma unroll
                    for (int j = 0; j < 8; j++)
                        mma_tf32(acc[i][j], af[i], bf[j]);
            }
            __syncthreads();
        }

        float* ob = out + (size_t)(bt * 64) * 256;
#pragma unroll
        for (int j = 0; j < 8; j++) {
            int col = 64 * wn + 8 * j + 2 * tig;
            float b0 = proj_b[col], b1 = proj_b[col + 1];
#pragma unroll
            for (int i = 0; i < 2; i++) {
                int r0 = 32 * wm + i * 16 + g, r1 = r0 + 8;
                *reinterpret_cast<float2*>(ob + (size_t)r0 * 256 + col) =
                    make_float2(acc[i][j][0] + b0, acc[i][j][1] + b1);
                *reinterpret_cast<float2*>(ob + (size_t)r1 * 256 + col) =
                    make_float2(acc[i][j][2] + b0, acc[i][j][3] + b1);
            }
        }
    }
}

// ---------------------------------------------------------------------------
extern "C" void kernel_launch(void* const* d_in, const int* in_sizes, int n_in,
                              void* d_out, int out_size)
{
    const float* x      = (const float*)d_in[0];
    const float* memory = (const float*)d_in[1];
    const float* q_w    = (const float*)d_in[2];
    const float* q_b    = (const float*)d_in[3];
    const float* kv_w   = (const float*)d_in[4];
    const float* kv_b   = (const float*)d_in[5];
    const float* proj_w = (const float*)d_in[6];
    const float* proj_b = (const float*)d_in[7];
    const float* rpb    = (const float*)d_in[8];
    float* out = (float*)d_out;

    float *pq, *pwq;
    cudaGetSymbolAddress((void**)&pq, g_q);
    cudaGetSymbolAddress((void**)&pwq, g_wq);

    cudaFuncSetAttribute(gemm_tf32, cudaFuncAttributeMaxDynamicSharedMemorySize,
                         GEMM_SMEM_BYTES);
    cudaFuncSetAttribute(mega, cudaFuncAttributeMaxDynamicSharedMemorySize,
                         MEGA_SMEM_BYTES);

    // fused prologue: bias table + tf32 weight conversions
    prolog<<<1152, 256>>>(rpb, q_w, kv_w, proj_w);
    // q = x @ q_w^T + q_b  (131072 x 256, K=256)
    gemm_tf32<<<dim3(2, 512), 256, GEMM_SMEM_BYTES>>>(x, pwq, q_b, pq,
                                                      BB * NTOK, CDIM, CDIM);
    // fused kv-proj + attention + out-proj, block per (b, t)
    mega<<<BB * TT, 256, MEGA_SMEM_BYTES>>>(memory, kv_b, proj_b, out);
}

// round 16
// speedup vs baseline: 1.2798x; 1.2798x over previous
#include <cuda_runtime.h>
#include <cstdint>

// Problem constants
#define BB 2048
#define TT 2
#define NTOK 64
#define CDIM 256
#define NH 8

// Scratch (device globals; allocation APIs are forbidden)
__device__ float g_q[(size_t)BB * NTOK * CDIM];
__device__ float g_kv[(size_t)BB * TT * NTOK * 2 * CDIM];
__device__ float g_attn[(size_t)BB * TT * NTOK * CDIM];
__device__ float g_bias[NH * NTOK * NTOK];      // [h][n][m] precomputed rpb
__device__ float g_wq[CDIM * CDIM];             // tf32-pre-converted weights
__device__ float g_wkv[2 * CDIM * CDIM];
__device__ float g_wp[CDIM * CDIM];

// ---- tf32 helpers -----------------------------------------------------------
__device__ __forceinline__ uint32_t f2tf32(float f) {
    uint32_t r;
    asm("cvt.rna.tf32.f32 %0, %1;" : "=r"(r) : "f"(f));
    return r;
}
__device__ __forceinline__ void mma_tf32(float c[4], const uint32_t a[4],
                                         const uint32_t b[2]) {
    asm("mma.sync.aligned.m16n8k8.row.col.f32.tf32.tf32.f32 "
        "{%0,%1,%2,%3}, {%4,%5,%6,%7}, {%8,%9}, {%0,%1,%2,%3};"
        : "+f"(c[0]), "+f"(c[1]), "+f"(c[2]), "+f"(c[3])
        : "r"(a[0]), "r"(a[1]), "r"(a[2]), "r"(a[3]), "r"(b[0]), "r"(b[1]));
}

// ---- cp.async helpers -------------------------------------------------------
__device__ __forceinline__ void cp16(float* smem_dst, const float* gsrc) {
    uint32_t s = (uint32_t)__cvta_generic_to_shared(smem_dst);
    asm volatile("cp.async.cg.shared.global [%0], [%1], 16;" :: "r"(s), "l"(gsrc));
}
__device__ __forceinline__ void cp_commit() {
    asm volatile("cp.async.commit_group;");
}
__device__ __forceinline__ void cp_wait1() {
    asm volatile("cp.async.wait_group 1;");
}
__device__ __forceinline__ void cp_wait0() {
    asm volatile("cp.async.wait_group 0;");
}

// ---------------------------------------------------------------------------
// Fused prologue: bias table + 3 weight tf32 conversions. 1152 blocks x 256.
// ---------------------------------------------------------------------------
__global__ __launch_bounds__(256) void prolog(
    const float* __restrict__ rpb, const float* __restrict__ qw,
    const float* __restrict__ kvw, const float* __restrict__ pw)
{
    int i = blockIdx.x * 256 + threadIdx.x;
    if (i < 32768) {
        int h = i >> 12, n = (i >> 6) & 63, m = i & 63;
        int idx = ((n >> 3) - (m >> 3) + 7) * 15 + ((n & 7) - (m & 7) + 7);
        g_bias[i] = rpb[idx * 8 + h];
    } else if (i < 98304) {
        int j = i - 32768;
        g_wq[j] = __uint_as_float(f2tf32(qw[j]));
    } else if (i < 229376) {
        int j = i - 98304;
        g_wkv[j] = __uint_as_float(f2tf32(kvw[j]));
    } else {
        int j = i - 229376;
        g_wp[j] = __uint_as_float(f2tf32(pw[j]));
    }
}

// ---------------------------------------------------------------------------
// TF32 GEMM (round-13 proven): C[M,N] = (A[M,K] @ W[N,K]^T + bias[N])*outscale
// 256x128 block tile, BK=32, 256 threads = 8 warps as 4M x 2N, 64x64 warp
// tiles. cp.async double-buffered. W PRE-CONVERTED tf32; A cvt at frag load.
// ---------------------------------------------------------------------------
#define A_TW (256 * 36)
#define W_TW (128 * 36)
#define GEMM_SMEM_BYTES (2 * (A_TW + W_TW) * 4)

__global__ __launch_bounds__(256, 1) void gemm_tf32(
    const float* __restrict__ A, const float* __restrict__ Wt,
    const float* __restrict__ bias, float* __restrict__ C,
    int M, int N, int K, float outscale)
{
    extern __shared__ float gsm[];
    float* Asm = gsm;
    float* Wsm = gsm + 2 * A_TW;

    const int tid  = threadIdx.x;
    const int wid  = tid >> 5;
    const int lane = tid & 31;
    const int g    = lane >> 2;
    const int tig  = lane & 3;
    const int bm = blockIdx.y * 256;
    const int bn = blockIdx.x * 128;
    const int warp_m = (wid >> 1) * 64;
    const int warp_n = (wid & 1) * 64;

    const int srow = tid >> 3;
    const int sc4  = (tid & 7) * 4;
    const float* Abase = A + (size_t)(bm + srow) * K + sc4;
    const float* Wbase = Wt + (size_t)(bn + srow) * K + sc4;

    float acc[4][8][4];
#pragma unroll
    for (int i = 0; i < 4; i++)
#pragma unroll
        for (int j = 0; j < 8; j++)
#pragma unroll
            for (int r = 0; r < 4; r++) acc[i][j][r] = 0.0f;

    const int nk = K >> 5;
    {
#pragma unroll
        for (int c = 0; c < 8; c++)
            cp16(Asm + (srow + 32 * c) * 36 + sc4, Abase + (size_t)(32 * c) * K);
#pragma unroll
        for (int c = 0; c < 4; c++)
            cp16(Wsm + (srow + 32 * c) * 36 + sc4, Wbase + (size_t)(32 * c) * K);
        cp_commit();
    }

    for (int kt = 0; kt < nk; kt++) {
        const int cur = kt & 1;
        if (kt + 1 < nk) {
            float* Ad = Asm + (1 - cur) * A_TW;
            float* Wd = Wsm + (1 - cur) * W_TW;
            const float* Ag = Abase + (kt + 1) * 32;
            const float* Wg = Wbase + (kt + 1) * 32;
#pragma unroll
            for (int c = 0; c < 8; c++)
                cp16(Ad + (srow + 32 * c) * 36 + sc4, Ag + (size_t)(32 * c) * K);
#pragma unroll
            for (int c = 0; c < 4; c++)
                cp16(Wd + (srow + 32 * c) * 36 + sc4, Wg + (size_t)(32 * c) * K);
            cp_commit();
            cp_wait1();
        } else {
            cp_wait0();
        }
        __syncthreads();

        const float* Ab = Asm + cur * A_TW;
        const float* Wb = Wsm + cur * W_TW;
#pragma unroll
        for (int kk = 0; kk < 4; kk++) {
            const int kb = kk * 8;
            uint32_t af[4][4], bf[8][2];
#pragma unroll
            for (int i = 0; i < 4; i++) {
                int row = warp_m + i * 16;
                af[i][0] = f2tf32(Ab[(row + g) * 36 + kb + tig]);
                af[i][1] = f2tf32(Ab[(row + 8 + g) * 36 + kb + tig]);
                af[i][2] = f2tf32(Ab[(row + g) * 36 + kb + tig + 4]);
                af[i][3] = f2tf32(Ab[(row + 8 + g) * 36 + kb + tig + 4]);
            }
#pragma unroll
            for (int j = 0; j < 8; j++) {
                int col = warp_n + j * 8 + g;
                bf[j][0] = __float_as_uint(Wb[col * 36 + kb + tig]);
                bf[j][1] = __float_as_uint(Wb[col * 36 + kb + tig + 4]);
            }
#pragma unroll
            for (int i = 0; i < 4; i++)
#pragma unroll
                for (int j = 0; j < 8; j++)
                    mma_tf32(acc[i][j], af[i], bf[j]);
        }
        __syncthreads();
    }

#pragma unroll
    for (int j = 0; j < 8; j++) {
        int col = bn + warp_n + j * 8 + tig * 2;
        float b0 = bias[col], b1 = bias[col + 1];
#pragma unroll
        for (int i = 0; i < 4; i++) {
            int row = bm + warp_m + i * 16 + g;
            float2 v0 = make_float2((acc[i][j][0] + b0) * outscale,
                                    (acc[i][j][1] + b1) * outscale);
            float2 v1 = make_float2((acc[i][j][2] + b0) * outscale,
                                    (acc[i][j][3] + b1) * outscale);
            *reinterpret_cast<float2*>(C + (size_t)row * N + col) = v0;
            *reinterpret_cast<float2*>(C + (size_t)(row + 8) * N + col) = v1;
        }
    }
}

// ---------------------------------------------------------------------------
// Tensor-core attention (R13 layout), cp.async split-group staging:
// group0 = Q+K (waited before QK^T), group1 = V (waited only before PV, so
// its load overlaps QK^T + softmax). Raw fp32 in smem; tf32 cvt at frag load.
// Block = one head: 128 threads = 4 warps; warp w owns rows 16w..16w+15.
// Smem (floats): Q[64x36]@0, K[64x36]@2304, V[64x40]@4608, S[64x68]@7168,
// inv_sum[64]@11520.  46,336 B -> 4 blocks/SM.
// ---------------------------------------------------------------------------
#define QOFF 0
#define KOFF 2304
#define VOFF 4608
#define SOFF 7168
#define SUMOFF 11520
#define ATTN_SMEM_BYTES ((11520 + 64) * 4)

__global__ __launch_bounds__(128) void attn_mma(void)
{
    extern __shared__ float S[];
    const int tid  = threadIdx.x;
    const int wid  = tid >> 5;
    const int lane = tid & 31;
    const int g    = lane >> 2;
    const int tig  = lane & 3;
    const int bx = blockIdx.x;
    const int h = bx & 7;
    const int t = (bx >> 3) & 1;
    const int b = bx >> 4;

    // ---- stage via cp.async: group0 = Q+K, group1 = V ----
    const float* qg = g_q + (size_t)(b * 64) * 256 + h * 32;      // pre-scaled
    const float* kg = g_kv + (size_t)((b * 2 + t) * 64) * 512 + h * 32;
#pragma unroll
    for (int it = 0; it < 4; it++) {
        int idx = tid + 128 * it;       // 0..511 float4s
        int r = idx >> 3, c4 = idx & 7;
        cp16(S + QOFF + r * 36 + c4 * 4, qg + (size_t)r * 256 + c4 * 4);
        cp16(S + KOFF + r * 36 + c4 * 4, kg + (size_t)r * 512 + c4 * 4);
    }
    cp_commit();
#pragma unroll
    for (int it = 0; it < 4; it++) {
        int idx = tid + 128 * it;
        int r = idx >> 3, c4 = idx & 7;
        cp16(S + VOFF + r * 40 + c4 * 4, kg + 256 + (size_t)r * 512 + c4 * 4);
    }
    cp_commit();
    cp_wait1();          // Q+K landed; V still in flight
    __syncthreads();

    // ---- QK^T: warp w computes rows 16w..16w+15 x all 64 cols (+bias) ----
    const int rb = wid * 16;
    {
        float acc[8][4];
#pragma unroll
        for (int j = 0; j < 8; j++)
#pragma unroll
            for (int r = 0; r < 4; r++) acc[j][r] = 0.0f;

#pragma unroll
        for (int k = 0; k < 4; k++) {
            uint32_t af[4];
            const float* q0 = S + QOFF + (rb + g) * 36 + 8 * k + tig;
            const float* q1 = S + QOFF + (rb + 8 + g) * 36 + 8 * k + tig;
            af[0] = f2tf32(q0[0]);
            af[1] = f2tf32(q1[0]);
            af[2] = f2tf32(q0[4]);
            af[3] = f2tf32(q1[4]);
#pragma unroll
            for (int jn = 0; jn < 8; jn++) {
                const float* kp = S + KOFF + (jn * 8 + g) * 36 + 8 * k + tig;
                uint32_t bf[2];
                bf[0] = f2tf32(kp[0]);
                bf[1] = f2tf32(kp[4]);
                mma_tf32(acc[jn], af, bf);
            }
        }
        const float* bh = g_bias + h * 4096;
#pragma unroll
        for (int jn = 0; jn < 8; jn++) {
            int cb = jn * 8 + 2 * tig;
            float2 bv0 = __ldg(reinterpret_cast<const float2*>(bh + (rb + g) * 64 + cb));
            float2 bv1 = __ldg(reinterpret_cast<const float2*>(bh + (rb + 8 + g) * 64 + cb));
            *reinterpret_cast<float2*>(S + SOFF + (rb + g) * 68 + cb) =
                make_float2(acc[jn][0] + bv0.x, acc[jn][1] + bv0.y);
            *reinterpret_cast<float2*>(S + SOFF + (rb + 8 + g) * 68 + cb) =
                make_float2(acc[jn][2] + bv1.x, acc[jn][3] + bv1.y);
        }
    }
    __syncthreads();

    // ---- softmax: 2 threads per row (half-row each), shfl-combined ----
    {
        const int r = tid >> 1;
        const int half = tid & 1;
        float* Sr = S + SOFF + r * 68 + half * 32;
        float mx = -1e30f;
#pragma unroll 8
        for (int m = 0; m < 32; m++) mx = fmaxf(mx, Sr[m]);
        mx = fmaxf(mx, __shfl_xor_sync(0xFFFFFFFFu, mx, 1));
        float sum = 0.0f;
#pragma unroll 8
        for (int m = 0; m < 32; m++) {
            float e = __expf(Sr[m] - mx);
            sum += e;
            Sr[m] = __uint_as_float(f2tf32(e));
        }
        sum += __shfl_xor_sync(0xFFFFFFFFu, sum, 1);
        if (half == 0) S[SUMOFF + r] = 1.0f / sum;
    }
    cp_wait0();          // V landed (overlapped with QK^T + softmax)
    __syncthreads();

    // ---- PV: warp w computes rows 16w..16w+15 x 32 dims ----
    float acc[4][4];
#pragma unroll
    for (int j = 0; j < 4; j++)
#pragma unroll
        for (int r = 0; r < 4; r++) acc[j][r] = 0.0f;

#pragma unroll
    for (int k = 0; k < 8; k++) {
        uint32_t ah[4];
        const float* p0 = S + SOFF + (rb + g) * 68 + 8 * k + tig;
        const float* p1 = S + SOFF + (rb + 8 + g) * 68 + 8 * k + tig;
        ah[0] = __float_as_uint(p0[0]);
        ah[1] = __float_as_uint(p1[0]);
        ah[2] = __float_as_uint(p0[4]);
        ah[3] = __float_as_uint(p1[4]);
        uint32_t bf[4][2];
#pragma unroll
        for (int j = 0; j < 4; j++) {
            const float* v0 = S + VOFF + (8 * k + tig) * 40 + 8 * j + g;
            const float* v1 = S + VOFF + (8 * k + tig + 4) * 40 + 8 * j + g;
            bf[j][0] = f2tf32(v0[0]);
            bf[j][1] = f2tf32(v1[0]);
        }
#pragma unroll
        for (int j = 0; j < 4; j++)
            mma_tf32(acc[j], ah, bf[j]);
    }

    // ---- epilogue ----
    float* og = g_attn + (size_t)((b * 2 + t) * 64) * 256 + h * 32;
    {
        float is0 = S[SUMOFF + rb + g];
        float is1 = S[SUMOFF + rb + 8 + g];
#pragma unroll
        for (int j = 0; j < 4; j++) {
            int d = 8 * j + 2 * tig;
            *reinterpret_cast<float2*>(og + (size_t)(rb + g) * 256 + d) =
                make_float2(acc[j][0] * is0, acc[j][1] * is0);
            *reinterpret_cast<float2*>(og + (size_t)(rb + 8 + g) * 256 + d) =
                make_float2(acc[j][2] * is1, acc[j][3] * is1);
        }
    }
}

// ---------------------------------------------------------------------------
extern "C" void kernel_launch(void* const* d_in, const int* in_sizes, int n_in,
                              void* d_out, int out_size)
{
    const float* x      = (const float*)d_in[0];
    const float* memory = (const float*)d_in[1];
    const float* q_w    = (const float*)d_in[2];
    const float* q_b    = (const float*)d_in[3];
    const float* kv_w   = (const float*)d_in[4];
    const float* kv_b   = (const float*)d_in[5];
    const float* proj_w = (const float*)d_in[6];
    const float* proj_b = (const float*)d_in[7];
    const float* rpb    = (const float*)d_in[8];
    float* out = (float*)d_out;

    float *pq, *pkv, *pattn, *pwq, *pwkv, *pwp;
    cudaGetSymbolAddress((void**)&pq, g_q);
    cudaGetSymbolAddress((void**)&pkv, g_kv);
    cudaGetSymbolAddress((void**)&pattn, g_attn);
    cudaGetSymbolAddress((void**)&pwq, g_wq);
    cudaGetSymbolAddress((void**)&pwkv, g_wkv);
    cudaGetSymbolAddress((void**)&pwp, g_wp);

    cudaFuncSetAttribute(gemm_tf32, cudaFuncAttributeMaxDynamicSharedMemorySize,
                         GEMM_SMEM_BYTES);
    cudaFuncSetAttribute(attn_mma, cudaFuncAttributeMaxDynamicSharedMemorySize,
                         ATTN_SMEM_BYTES);

    const float scale = 0.17677669529663687f;  // 32^-0.5

    // fused prologue: bias table + tf32 weight conversions
    prolog<<<1152, 256>>>(rpb, q_w, kv_w, proj_w);
    // q = (x @ q_w^T + q_b) * scale   (131072 x 256, K=256)
    gemm_tf32<<<dim3(2, 512), 256, GEMM_SMEM_BYTES>>>(x, pwq, q_b, pq,
                                                      BB * NTOK, CDIM, CDIM, scale);
    // kv = memory @ kv_w^T + kv_b     (262144 x 512, K=256)
    gemm_tf32<<<dim3(4, 1024), 256, GEMM_SMEM_BYTES>>>(memory, pwkv, kv_b, pkv,
                                                       BB * TT * NTOK, 2 * CDIM, CDIM, 1.0f);
    // attention: block = (b, t, h)
    attn_mma<<<BB * TT * NH, 128, ATTN_SMEM_BYTES>>>();
    // out = attn @ proj_w^T + proj_b  (262144 x 256, K=256)
    gemm_tf32<<<dim3(2, 1024), 256, GEMM_SMEM_BYTES>>>(pattn, pwp, proj_b, out,
                                                       BB * TT * NTOK, CDIM, CDIM, 1.0f);
}